// round 8
// baseline (speedup 1.0000x reference)
#include <cuda_runtime.h>
#include <cstdint>

// CIC deposition: 10M particles -> 256^3 float grid.
// Round 8: grid A = d_out (standard layout), z-pairs deposited with ONE v4 RED
// when the pair sits inside a 16B quad (cz%4 != 3, 75%), otherwise ONE v2 RED
// into a compact overflow grid B[x][y][k] holding pairs (z=4k+3, z=4k+4)
// (33.5MB). Exactly 1 active RED per (x,y) row -> 4 active REDs/particle,
// 40M dense REDs, total atomic footprint 97.5MB (< L2). Merge folds B into
// d_out. No depermute pass needed.

static constexpr int   NC    = 256;
static constexpr float GMINF = -10.0f;
static constexpr float DXF   = (float)(20.0 / 255.0);

static constexpr size_t NB2 = 256u * 256u * 64u;        // 4.19M float2 = 33.5MB
__device__ __align__(16) float2 g_B[NB2];

__global__ void zero_out_kernel(float4* __restrict__ out, int n4) {
    int i = blockIdx.x * blockDim.x + threadIdx.x;
    if (i < n4) out[i] = make_float4(0.f, 0.f, 0.f, 0.f);
}

__global__ void zero_B_kernel(int n4) {
    int i = blockIdx.x * blockDim.x + threadIdx.x;
    if (i < n4) ((float4*)g_B)[i] = make_float4(0.f, 0.f, 0.f, 0.f);
}

__device__ __forceinline__ void red_v4p(float* p, float a, float b, float c, float d, int pred) {
    asm volatile(
        "{\n\t"
        ".reg .pred q;\n\t"
        "setp.ne.s32 q, %5, 0;\n\t"
        "@q red.global.add.v4.f32 [%0], {%1, %2, %3, %4};\n\t"
        "}"
        :: "l"(p), "f"(a), "f"(b), "f"(c), "f"(d), "r"(pred) : "memory");
}

__device__ __forceinline__ void red_v2p(float* p, float a, float b, int pred) {
    asm volatile(
        "{\n\t"
        ".reg .pred q;\n\t"
        "setp.ne.s32 q, %3, 0;\n\t"
        "@q red.global.add.v2.f32 [%0], {%1, %2};\n\t"
        "}"
        :: "l"(p), "f"(a), "f"(b), "r"(pred) : "memory");
}

__device__ __forceinline__ void deposit_one(
    float px, float py_, float pz, float w, float* __restrict__ grid)
{
    // Match JAX float32 arithmetic: subtract then IEEE divide
    float fx = (px  - GMINF) / DXF;
    float fy = (py_ - GMINF) / DXF;
    float fz = (pz  - GMINF) / DXF;

    float ixf = floorf(fx), iyf = floorf(fy), izf = floorf(fz);
    int cx = (int)ixf, cy = (int)iyf, cz = (int)izf;

    if ((unsigned)cx > 255u || (unsigned)cy > 255u || (unsigned)cz > 255u) return;

    float ox = fx - ixf, oy = fy - iyf, oz = fz - izf;

    // corner weight = ((w * X) * Y) * Z (reference association)
    float wx0 = w * (1.0f - ox);
    float wx1 = w * ox;
    float y0 = 1.0f - oy, y1 = oy;
    float z0 = 1.0f - oz, z1 = oz;

    bool bx = cx < (NC - 1);
    bool by = cy < (NC - 1);

    int  m    = cz & 3;                 // position of cz within aligned quad
    int  use4 = (m != 3);               // z-pair fits in one 16B quad
    int  useB = !use4;                  // overflow pair (z=4k+3, 4k+4)
    // 0/1 lane masks as floats: lane L receives v0*aL + v1*a(L-1)
    float a0 = (m == 0) ? 1.0f : 0.0f;
    float a1 = (m == 1) ? 1.0f : 0.0f;
    float a2 = (m == 2) ? 1.0f : 0.0f;

    float* g  = grid + (((size_t)cx * NC + (size_t)cy) * NC + (size_t)cz);
    float* gq = g - m;                  // 16B-aligned quad base
    const size_t SX = (size_t)NC * NC;  // 65536
    const size_t SY = NC;               // 256

    // overflow slot: k = cz>>2 (valid when cz%4==3); row steps in float2 units
    int bk = cz >> 2;
    float2* B0 = g_B + (((size_t)cx * NC + (size_t)cy) * 64 + (size_t)bk);
    const size_t BX = (size_t)NC * 64;  // 16384
    const size_t BY = 64;

    #define DEPOSIT_ROW(goff, boff, rw)  do {                                 \
        float v0 = (rw) * z0;                                                 \
        float v1 = (rw) * z1;                                                 \
        float l0 = v0 * a0;                                                   \
        float l1 = fmaf(v1, a0, v0 * a1);                                     \
        float l2 = fmaf(v1, a1, v0 * a2);                                     \
        float l3 = v1 * a2;                                                   \
        red_v4p(gq + (goff), l0, l1, l2, l3, use4);                           \
        red_v2p((float*)(B0 + (boff)), v0, v1, useB);                         \
    } while (0)

    DEPOSIT_ROW(0, 0, wx0 * y0);
    if (by) DEPOSIT_ROW(SY, BY, wx0 * y1);
    if (bx) {
        DEPOSIT_ROW(SX, BX, wx1 * y0);
        if (by) DEPOSIT_ROW(SX + SY, BX + BY, wx1 * y1);
    }
    #undef DEPOSIT_ROW
}

__global__ void __launch_bounds__(256) cic_deposit_kernel(
    const float* __restrict__ pos,
    const float* __restrict__ wgt,
    float* __restrict__ grid,
    int n)
{
    int t = blockIdx.x * blockDim.x + threadIdx.x;
    int base = 4 * t;
    if (base >= n) return;

    if (base + 3 < n) {
        const float4* p4 = (const float4*)pos + 3 * (size_t)t;
        float4 A = __ldcs(p4 + 0);
        float4 B = __ldcs(p4 + 1);
        float4 C = __ldcs(p4 + 2);
        float4 W = __ldcs((const float4*)wgt + t);

        deposit_one(A.x, A.y, A.z, W.x, grid);
        deposit_one(A.w, B.x, B.y, W.y, grid);
        deposit_one(B.z, B.w, C.x, W.z, grid);
        deposit_one(C.y, C.z, C.w, W.w, grid);
    } else {
        for (int i = base; i < n; i++) {
            float ppx = __ldcs(pos + 3 * (size_t)i + 0);
            float ppy = __ldcs(pos + 3 * (size_t)i + 1);
            float ppz = __ldcs(pos + 3 * (size_t)i + 2);
            float ww  = __ldcs(wgt + i);
            deposit_one(ppx, ppy, ppz, ww, grid);
        }
    }
}

// merge overflow pairs into out: B[x][y][k] -> out[x][y][4k+3] (+ [4k+4] if <256)
__global__ void __launch_bounds__(256) merge_B_kernel(float* __restrict__ out, int nb) {
    int id = blockIdx.x * blockDim.x + threadIdx.x;
    if (id >= nb) return;
    int k  = id & 63;
    int xy = id >> 6;                 // x*256 + y

    float2 b = __ldcs((const float*)nullptr == nullptr ? &g_B[id] : &g_B[id]);
    int z = 4 * k + 3;
    float* o = out + ((size_t)xy << 8) + (size_t)z;
    o[0] += b.x;
    if (z + 1 < 256) o[1] += b.y;     // k==63 pair half z=256 is cropped
}

extern "C" void kernel_launch(void* const* d_in, const int* in_sizes, int n_in,
                              void* d_out, int out_size) {
    const float* positions = (const float*)d_in[0];
    const float* weights   = (const float*)d_in[1];
    float* grid = (float*)d_out;

    int n_particles = in_sizes[1];  // weights element count = N

    // 1) zero d_out (grid A) and the overflow grid B
    int n4 = out_size / 4;
    zero_out_kernel<<<(n4 + 255) / 256, 256>>>((float4*)grid, n4);
    int nb4 = (int)(NB2 / 2);       // float2 pairs -> float4 count
    zero_B_kernel<<<(nb4 + 255) / 256, 256>>>(nb4);

    // 2) single dense deposit pass: 4 active REDs/particle
    int n_threads_total = (n_particles + 3) / 4;
    int threads = 256;
    int blocks = (n_threads_total + threads - 1) / threads;
    cic_deposit_kernel<<<blocks, threads>>>(positions, weights, grid, n_particles);

    // 3) fold overflow pairs into d_out
    int nb = (int)NB2;
    merge_B_kernel<<<(nb + 255) / 256, 256>>>(grid, nb);
}

// round 9
// speedup vs baseline: 1.5470x; 1.5470x over previous
#include <cuda_runtime.h>
#include <cstdint>

// CIC deposition: 10M particles -> 256^3 float grid.
// Round 9: R7's parity-adaptive y-pairing (3 active RED lanes/particle, two
// 64MB grids, two passes so the hot footprint stays 64MB) PLUS a per-warp
// SMEM compaction ring so dense deposit rounds always run with 32 active
// lanes (R7 lost ~0.9 cyc/lane to 50% predication; this removes it).

static constexpr float GMINF = -10.0f;
static constexpr float DXF   = (float)(20.0 / 255.0);

static constexpr size_t XSTRIDE = 128u * 128u * 4u;   // 65536 floats per x row
static constexpr size_t GRIDF   = 256u * XSTRIDE;     // 16,777,216 floats = 64MB
__device__ __align__(16) float g_scratch[2 * GRIDF];  // grid A (pass0), grid B (pass1)

__global__ void zero_scratch_kernel(int n4) {
    int i = blockIdx.x * blockDim.x + threadIdx.x;
    if (i < n4) ((float4*)g_scratch)[i] = make_float4(0.f, 0.f, 0.f, 0.f);
}

__device__ __forceinline__ void red_v4(float* p, float a, float b, float c, float d) {
    asm volatile("red.global.add.v4.f32 [%0], {%1, %2, %3, %4};"
                 :: "l"(p), "f"(a), "f"(b), "f"(c), "f"(d) : "memory");
}

__device__ __forceinline__ void red_v4p(float* p, float a, float b, float c, float d, int pred) {
    asm volatile(
        "{\n\t"
        ".reg .pred q;\n\t"
        "setp.ne.s32 q, %5, 0;\n\t"
        "@q red.global.add.v4.f32 [%0], {%1, %2, %3, %4};\n\t"
        "}"
        :: "l"(p), "f"(a), "f"(b), "f"(c), "f"(d), "r"(pred) : "memory");
}

struct Derived {
    float wx0, wx1, t0, t1, t2, t3, u0, u2;
    unsigned pack;   // quad index (24b) | spill flag <<24 | x-row2 flag <<25
};

__device__ __forceinline__ bool compute_derived(
    const float* __restrict__ pos, const float* __restrict__ wgt,
    int i, int n, int pass, Derived& d)
{
    if (i >= n) return false;
    float px = __ldcs(pos + 3 * (size_t)i + 0);
    float py = __ldcs(pos + 3 * (size_t)i + 1);
    float pz = __ldcs(pos + 3 * (size_t)i + 2);
    float w  = __ldcs(wgt + i);

    // Match JAX float32 arithmetic: subtract then IEEE divide
    float fx = (px - GMINF) / DXF;
    float fy = (py - GMINF) / DXF;
    float fz = (pz - GMINF) / DXF;

    float ixf = floorf(fx), iyf = floorf(fy), izf = floorf(fz);
    int cx = (int)ixf, cy = (int)iyf, cz = (int)izf;

    if ((unsigned)cx > 255u || (unsigned)cy > 255u || (unsigned)cz > 255u) return false;
    if ((cy & 1) != pass) return false;

    float ox = fx - ixf, oy = fy - iyf, oz = fz - izf;

    float wx0 = w * (1.0f - ox);
    float wx1 = w * ox;
    float wy0 = 1.0f - oy, wy1 = oy;
    float wz0 = 1.0f - oz, wz1 = oz;

    int odd = cz & 1;
    // quad lanes [ybit*2 + zbit] at z-block Bz: zb0 -> z=2Bz, zb1 -> z=2Bz+1
    float zA0 = odd ? 0.0f : wz0;
    float zA1 = odd ? wz0  : wz1;

    d.wx0 = wx0; d.wx1 = wx1;
    d.t0 = wy0 * zA0; d.t1 = wy0 * zA1; d.t2 = wy1 * zA0; d.t3 = wy1 * zA1;
    d.u0 = wy0 * wz1; d.u2 = wy1 * wz1;           // spill quad (odd cz only)

    unsigned By = (unsigned)(cy >> 1);
    unsigned Bz = (unsigned)(cz >> 1);
    unsigned idx = ((unsigned)cx * 128u + By) * 128u + Bz;   // < 2^24
    unsigned sflag = (unsigned)(odd & (cz < 255));
    unsigned bxf   = (unsigned)(cx < 255);
    d.pack = idx | (sflag << 24) | (bxf << 25);
    return true;
}

__device__ __forceinline__ void deposit_dense(
    float* __restrict__ G,
    float wx0, float wx1, float t0, float t1, float t2, float t3,
    float u0, float u2, unsigned pack, int p)
{
    unsigned idx = pack & 0xFFFFFFu;
    int sp = (int)((pack >> 24) & 1u);
    int bx = (int)((pack >> 25) & 1u);
    float* b0 = G + (size_t)idx * 4;

    red_v4p(b0,                   wx0 * t0, wx0 * t1, wx0 * t2, wx0 * t3, p);
    red_v4p(b0 + 4,               wx0 * u0, 0.0f,     wx0 * u2, 0.0f,     p & sp);
    red_v4p(b0 + XSTRIDE,         wx1 * t0, wx1 * t1, wx1 * t2, wx1 * t3, p & bx);
    red_v4p(b0 + XSTRIDE + 4,     wx1 * u0, 0.0f,     wx1 * u2, 0.0f,     p & sp & bx);
}

static constexpr int NWARPS  = 8;     // 256 threads / block
static constexpr int RING    = 128;   // slots per warp (power of 2)
static constexpr int FIELDS  = 9;

__global__ void __launch_bounds__(256) cic_deposit_kernel(
    const float* __restrict__ pos,
    const float* __restrict__ wgt,
    int n, int pass)
{
    __shared__ float q[NWARPS][RING * FIELDS];   // 36 KB

    float* G = g_scratch + (size_t)pass * GRIDF;
    int lane = threadIdx.x & 31;
    int wid  = threadIdx.x >> 5;
    float* Q = q[wid];

    int warp_global = blockIdx.x * NWARPS + wid;
    int total_warps = gridDim.x * NWARPS;
    int n_windows   = (n + 63) >> 6;

    unsigned head = 0, count = 0;
    unsigned lt = (1u << lane) - 1u;

    for (int wnd = warp_global; wnd < n_windows; wnd += total_warps) {
        int base = wnd << 6;
        Derived A, B;
        bool a0 = compute_derived(pos, wgt, base + lane,      n, pass, A);
        bool a1 = compute_derived(pos, wgt, base + 32 + lane, n, pass, B);
        unsigned m0 = __ballot_sync(0xffffffffu, a0);
        unsigned m1 = __ballot_sync(0xffffffffu, a1);
        unsigned n0 = __popc(m0);

        if (a0) {
            float* s = Q + (size_t)((head + count + __popc(m0 & lt)) & (RING - 1)) * FIELDS;
            s[0] = A.wx0; s[1] = A.wx1; s[2] = A.t0; s[3] = A.t1;
            s[4] = A.t2;  s[5] = A.t3;  s[6] = A.u0; s[7] = A.u2;
            s[8] = __uint_as_float(A.pack);
        }
        if (a1) {
            float* s = Q + (size_t)((head + count + n0 + __popc(m1 & lt)) & (RING - 1)) * FIELDS;
            s[0] = B.wx0; s[1] = B.wx1; s[2] = B.t0; s[3] = B.t1;
            s[4] = B.t2;  s[5] = B.t3;  s[6] = B.u0; s[7] = B.u2;
            s[8] = __uint_as_float(B.pack);
        }
        count += n0 + __popc(m1);
        __syncwarp();

        while (count >= 32) {
            const float* s = Q + (size_t)((head + lane) & (RING - 1)) * FIELDS;
            float wx0 = s[0], wx1 = s[1], t0 = s[2], t1 = s[3];
            float t2 = s[4], t3 = s[5], u0 = s[6], u2 = s[7];
            unsigned pack = __float_as_uint(s[8]);
            deposit_dense(G, wx0, wx1, t0, t1, t2, t3, u0, u2, pack, 1);
            head = (head + 32) & (RING - 1);
            count -= 32;
            __syncwarp();   // slots consumed before next window's appends reuse them
        }
    }

    // flush residual (< 32 particles per warp)
    if (count) {
        const float* s = Q + (size_t)((head + lane) & (RING - 1)) * FIELDS;
        int p = lane < (int)count;
        float wx0 = s[0], wx1 = s[1], t0 = s[2], t1 = s[3];
        float t2 = s[4], t3 = s[5], u0 = s[6], u2 = s[7];
        unsigned pack = __float_as_uint(s[8]);
        deposit_dense(G, wx0, wx1, t0, t1, t2, t3, u0, u2, pack, p);
    }
}

// merge: out[x][y][z] = A(x,y,z) + B(x,y,z); thread makes float4 of 4 z values.
__global__ void __launch_bounds__(256) merge_kernel(float4* __restrict__ out, int n4) {
    int t = blockIdx.x * blockDim.x + threadIdx.x;
    if (t >= n4) return;
    int z4 = t & 63;             // z = 4*z4 .. 4*z4+3
    int y  = (t >> 6) & 255;
    int x  = t >> 14;

    // grid A: By = y>>1, ybit = y&1
    const float* a = g_scratch
        + ((((size_t)x * 128 + (size_t)(y >> 1)) * 128 + (size_t)(z4 << 1)) << 2)
        + (size_t)((y & 1) << 1);
    float2 a0 = *(const float2*)a;
    float2 a1 = *(const float2*)(a + 4);
    float4 r = make_float4(a0.x, a0.y, a1.x, a1.y);

    if (y > 0) {
        // grid B: y = 2By+1+ybit -> By = (y-1)>>1, ybit = (y-1)&1
        int yb = y - 1;
        const float* b = g_scratch + GRIDF
            + ((((size_t)x * 128 + (size_t)(yb >> 1)) * 128 + (size_t)(z4 << 1)) << 2)
            + (size_t)((yb & 1) << 1);
        float2 b0 = *(const float2*)b;
        float2 b1 = *(const float2*)(b + 4);
        r.x += b0.x; r.y += b0.y; r.z += b1.x; r.w += b1.y;
    }
    out[t] = r;
}

extern "C" void kernel_launch(void* const* d_in, const int* in_sizes, int n_in,
                              void* d_out, int out_size) {
    const float* positions = (const float*)d_in[0];
    const float* weights   = (const float*)d_in[1];
    float* grid = (float*)d_out;

    int n_particles = in_sizes[1];  // weights element count = N

    // 1) zero both scratch grids (128MB)
    int nz4 = (int)(2 * GRIDF / 4);
    zero_scratch_kernel<<<(nz4 + 255) / 256, 256>>>(nz4);

    // 2) two compacted deposit passes (one 64MB grid hot per pass)
    int blocks = 148 * 4;   // 4736 warps, grid-stride over 64-particle windows
    cic_deposit_kernel<<<blocks, 256>>>(positions, weights, n_particles, 0);
    cic_deposit_kernel<<<blocks, 256>>>(positions, weights, n_particles, 1);

    // 3) merge parity grids into output (fully overwrites d_out)
    int n4 = out_size / 4;
    merge_kernel<<<(n4 + 255) / 256, 256>>>((float4*)grid, n4);
}